// round 1
// baseline (speedup 1.0000x reference)
#include <cuda_runtime.h>
#include <cstdint>

// ESN: out[b,p,l] via elementwise-diagonal recurrence.
// B=32, D_IN=64, D_STATE=1024, L=2048, LEAK=0.5
#define BB 32
#define DIN 64
#define DST 1024
#define LL 2048
#define TT 32      // timestep chunk
#define PTILE 128  // p-states per block (= blockDim.x)

__device__ __forceinline__ unsigned long long pack2(float a, float b) {
    unsigned long long r;
    asm("mov.b64 %0,{%1,%2};" : "=l"(r) : "f"(a), "f"(b));
    return r;
}
__device__ __forceinline__ void unpack2(unsigned long long v, float& a, float& b) {
    asm("mov.b64 {%0,%1},%2;" : "=f"(a), "=f"(b) : "l"(v));
}
// Packed dual-FMA: 2 fp32 FMAs per instruction (fma pipe, 2x throughput vs FFMA).
__device__ __forceinline__ void ffma2(unsigned long long& acc,
                                      unsigned long long a, unsigned long long b) {
    asm("fma.rn.f32x2 %0,%1,%2,%0;" : "+l"(acc) : "l"(a), "l"(b));
}
// Accurate-enough tanh (~1e-6 rel err), flag-independent, no overflow path.
__device__ __forceinline__ float fast_tanh(float v) {
    float a = fabsf(v);
    float e = __expf(-2.0f * a);           // in (0,1]
    float r = __fdividef(1.0f - e, 1.0f + e);
    return copysignf(r, v);
}

__global__ __launch_bounds__(PTILE) void esn_kernel(
    const float* __restrict__ u,      // [B, DIN, L]
    const float* __restrict__ w_in,   // [DST, DIN]
    const float* __restrict__ w_hh,   // [DST, DST] (diagonal used)
    const float* __restrict__ bias,   // [DST]
    float* __restrict__ out)          // [B, DST, L]
{
    __shared__ __align__(16) float su[TT][68];       // [t][h], pad 64->68 (16B-mult stride)
    __shared__ float tile[PTILE][TT + 1];            // output transpose tile

    const int tid = threadIdx.x;
    const int b  = blockIdx.y;
    const int p0 = blockIdx.x * PTILE;
    const int p  = p0 + tid;

    // Cache this thread's w_in row as 32 packed f32x2 values (64 regs).
    unsigned long long W2[DIN / 2];
    const float4* wrow = (const float4*)(w_in + (size_t)p * DIN);
#pragma unroll
    for (int i = 0; i < DIN / 4; i++) {
        float4 v = wrow[i];
        W2[2 * i]     = pack2(v.x, v.y);
        W2[2 * i + 1] = pack2(v.z, v.w);
    }
    const float d_p    = w_hh[(size_t)p * DST + p];  // diagonal element
    const float bias_p = bias[p];

    const float* ub = u + (size_t)b * DIN * LL;
    float*       ob = out + ((size_t)b * DST + p0) * LL;

    float x = 0.0f;

    for (int l0 = 0; l0 < LL; l0 += TT) {
        // ---- stage u[b, :, l0:l0+TT] into su[t][h] (transposed) ----
#pragma unroll
        for (int k = 0; k < 4; k++) {
            int idx = tid + k * PTILE;        // 0..511, covers 64h x 8 quads
            int h   = idx >> 3;
            int tq  = (idx & 7) << 2;
            float4 v = *(const float4*)(ub + (size_t)h * LL + l0 + tq);
            su[tq + 0][h] = v.x;
            su[tq + 1][h] = v.y;
            su[tq + 2][h] = v.z;
            su[tq + 3][h] = v.w;
        }
        __syncthreads();

        // ---- 32 recurrence steps; dots are x-independent -> ILP hides tanh ----
#pragma unroll
        for (int t = 0; t < TT; t++) {
            const ulonglong2* s = (const ulonglong2*)(&su[t][0]);  // 16B-aligned, broadcast
            unsigned long long acc0 = pack2(bias_p, 0.0f);
            unsigned long long acc1 = 0ull;
#pragma unroll
            for (int i = 0; i < 16; i++) {
                ulonglong2 sv = s[i];          // LDS.128 broadcast (no conflict)
                ffma2(acc0, W2[2 * i],     sv.x);
                ffma2(acc1, W2[2 * i + 1], sv.y);
            }
            float a0, a1, a2, a3;
            unpack2(acc0, a0, a1);
            unpack2(acc1, a2, a3);
            float pre = fmaf(d_p, x, (a0 + a1) + (a2 + a3));
            x = fmaf(0.5f, fast_tanh(pre), 0.5f * x);
            tile[tid][t] = x;                  // bank-conflict-free (stride 33)
        }
        __syncthreads();

        // ---- coalesced output write via transpose tile ----
#pragma unroll
        for (int r = 0; r < TT; r++) {
            int row = (tid >> 5) + r * 4;      // 4 warps x 32 iters = 128 rows
            int col = tid & 31;
            ob[(size_t)row * LL + l0 + col] = tile[row][col];
        }
        __syncthreads();   // protects tile & su for next chunk
    }
}

extern "C" void kernel_launch(void* const* d_in, const int* in_sizes, int n_in,
                              void* d_out, int out_size) {
    const float* u    = (const float*)d_in[0];
    const float* w_in = (const float*)d_in[1];
    const float* w_hh = (const float*)d_in[2];
    const float* bias = (const float*)d_in[3];
    float* out = (float*)d_out;

    dim3 grid(DST / PTILE, BB);   // (8, 32) = 256 blocks
    esn_kernel<<<grid, PTILE>>>(u, w_in, w_hh, bias, out);
}